// round 10
// baseline (speedup 1.0000x reference)
#include <cuda_runtime.h>
#include <math.h>

#define NTHREADS 256
#define TOPK_K   200
#define PARTS    32
#define CAND_CAP 2048

// ---------------------------------------------------------------------------
// d^2 with a fixed, non-FMA operation order so every recompute produces
// bit-identical keys.
__device__ __forceinline__ unsigned int compute_key(
    float vx, float vy, float vz, const float* __restrict__ fp, int i)
{
    float dx = __fsub_rn(vx, fp[3 * i + 0]);
    float dy = __fsub_rn(vy, fp[3 * i + 1]);
    float dz = __fsub_rn(vz, fp[3 * i + 2]);
    float d2 = __fadd_rn(__fadd_rn(__fmul_rn(dx, dx), __fmul_rn(dy, dy)),
                         __fmul_rn(dz, dz));
    return __float_as_uint(d2);   // d2 >= 0, so uint order == float order
}

// Replicates the reference's per-point bin computation for rel = q_j - q_0.
__device__ __forceinline__ void process_point(
    int i, const float* __restrict__ fp,
    float q0x, float q0y, float q0z,
    unsigned int* counts)
{
    const float TWO_PI_F = 6.28318530717958647692f;
    const float PI_F     = 3.14159265358979323846f;

    float rx = __fsub_rn(fp[3 * i + 0], q0x);
    float ry = __fsub_rn(fp[3 * i + 1], q0y);
    float rz = __fsub_rn(fp[3 * i + 2], q0z);

    float axy = fmodf(atan2f(ry, rx) + TWO_PI_F, TWO_PI_F);
    float azy = fmodf(atan2f(ry, rz) + TWO_PI_F, PI_F);
    int xyb = (int)floorf(axy / (TWO_PI_F * 0.25f));
    int zyb = (int)floorf(azy / (PI_F * 0.25f));

    float d2 = __fadd_rn(__fadd_rn(__fmul_rn(rx, rx), __fmul_rn(ry, ry)),
                         __fmul_rn(rz, rz));
    float D = sqrtf(__fadd_rn(d2, 1e-7f));
    int dist = (D >= 4.0f) ? 1 : ((D >= 1.0f) ? 0 : -1);

    if (dist >= 0 && xyb >= 0 && zyb >= 0) {
        int bin = dist * 16 + xyb * 4 + zyb;
        if (bin >= 0 && bin < PARTS) atomicAdd(&counts[bin], 1u);
    }
}

// Parallel "digit where cumulative count reaches `need`" over a 256-bin
// histogram. Warp 0 computes; results broadcast via shared. (Verbatim from
// the 137us kernel, plus s_cnt out for the early-exit check.)
__device__ __forceinline__ void find_digit(
    unsigned int* hist, int need, int t,
    unsigned int* s_digit, int* s_need, unsigned int* s_cnt)
{
    if (t < 32) {
        int base = t * 8;
        int s = 0;
        #pragma unroll
        for (int j = 0; j < 8; ++j) s += (int)hist[base + j];
        int cum = s;
        #pragma unroll
        for (int o = 1; o < 32; o <<= 1) {
            int v = __shfl_up_sync(0xFFFFFFFFu, cum, o);
            if (t >= o) cum += v;
        }
        unsigned int bal = __ballot_sync(0xFFFFFFFFu, cum >= need);
        int lane = __ffs(bal) - 1;
        if (t == lane) {
            int c = cum - s;   // exclusive prefix at this lane's first bin
            int d = base;
            while (c + (int)hist[d] < need) { c += (int)hist[d]; ++d; }
            *s_digit = (unsigned int)d;
            *s_need = need - c;
            *s_cnt = hist[d];
        }
    }
    __syncthreads();
}

__global__ __launch_bounds__(NTHREADS)
void scp_topk_bins_kernel(const float* __restrict__ vp,
                          const float* __restrict__ fp,
                          float* __restrict__ out,
                          int n_fp)
{
    __shared__ unsigned int hist[256];
    __shared__ unsigned long long cand[CAND_CAP];  // (key<<32)|idx
    __shared__ unsigned int counts[PARTS];
    __shared__ unsigned long long minpack;
    __shared__ unsigned int s_cand_count;
    __shared__ unsigned int s_digit;
    __shared__ int s_need;
    __shared__ unsigned int s_cnt;
    extern __shared__ unsigned char digits[];      // top byte per point

    const int b = blockIdx.x;
    const int t = threadIdx.x;

    const float vx = vp[3 * b + 0];
    const float vy = vp[3 * b + 1];
    const float vz = vp[3 * b + 2];

    if (t < PARTS) counts[t] = 0;
    if (t == 0) { minpack = ~0ull; s_cand_count = 0; }
    hist[t] = 0;
    const int nwords = (n_fp + 3) >> 2;
    // Pad trailing digit bytes so pass B's word scan sees 0xFF there.
    if (t < nwords * 4 - n_fp) digits[n_fp + t] = 0xFFu;
    __syncthreads();

    const int niter = (n_fp + NTHREADS - 1) / NTHREADS;
    unsigned int* __restrict__ digw = (unsigned int*)digits;

    // ---- Pass A (only full global scan): key per point (scalar loads, as in
    // the 137us kernel), digit byte -> smem, warp-aggregated digit histogram,
    // scalar running min (strict < keeps lowest index per thread).
    unsigned int kmin = 0xFFFFFFFFu;
    unsigned int imin = 0;
    for (int it = 0; it < niter; ++it) {
        int i = it * NTHREADS + t;
        bool valid = (i < n_fp);
        unsigned int active = __ballot_sync(0xFFFFFFFFu, valid);
        if (valid) {
            unsigned int k = compute_key(vx, vy, vz, fp, i);
            unsigned int d = k >> 24;
            digits[i] = (unsigned char)d;
            unsigned int peers = __match_any_sync(active, d);
            int leader = __ffs(peers) - 1;
            if ((int)(t & 31) == leader)
                atomicAdd(&hist[d], (unsigned int)__popc(peers));
            if (k < kmin) { kmin = k; imin = (unsigned int)i; }
        }
    }
    // Packed warp-reduce min (lowest index on key ties), one atomic per warp.
    {
        unsigned long long lmin =
            ((unsigned long long)kmin << 32) | (unsigned long long)imin;
        #pragma unroll
        for (int o = 16; o > 0; o >>= 1) {
            unsigned long long v = __shfl_xor_sync(0xFFFFFFFFu, lmin, o);
            if (v < lmin) lmin = v;
        }
        if ((t & 31) == 0) atomicMin(&minpack, lmin);
    }
    __syncthreads();

    find_digit(hist, TOPK_K, t, &s_digit, &s_need, &s_cnt);
    const unsigned int d0 = s_digit;
    const int need = s_need;

    // Anchor = nearest fusion point (lowest index on key ties).
    const unsigned int amin = (unsigned int)(minpack & 0xFFFFFFFFull);
    const float q0x = fp[3 * amin + 0];
    const float q0y = fp[3 * amin + 1];
    const float q0z = fp[3 * amin + 2];

    // ---- Pass B: smem digit scan, SIMD byte classification.
    // digit < d0  -> definitely in top-K: process immediately.
    // digit == d0 -> candidate: recompute key (scalar, bit-identical), compact.
    const unsigned int d0x4 = d0 * 0x01010101u;
    for (int w = t; w < nwords; w += NTHREADS) {
        unsigned int dw = digw[w];
        unsigned int lt = __vcmpltu4(dw, d0x4);
        unsigned int eq = __vcmpeq4(dw, d0x4);
        if (lt) {
            #pragma unroll
            for (int j = 0; j < 4; ++j)
                if ((lt >> (8 * j)) & 1u)
                    process_point(4 * w + j, fp, q0x, q0y, q0z, counts);
        }
        if (eq) {
            #pragma unroll
            for (int j = 0; j < 4; ++j)
                if ((eq >> (8 * j)) & 1u) {
                    int i = 4 * w + j;
                    if (i < n_fp) {
                        unsigned int k = compute_key(vx, vy, vz, fp, i);
                        unsigned int p = atomicAdd(&s_cand_count, 1u);
                        if (p < CAND_CAP)
                            cand[p] = ((unsigned long long)k << 32) |
                                      (unsigned long long)(unsigned int)i;
                    }
                }
        }
    }
    __syncthreads();
    const unsigned int nc = s_cand_count;

    if (nc <= CAND_CAP) {
        // ---- Exact need-th smallest packed (key,idx) among candidates via
        // 8-bit radix passes with early exit. Packed ordering reproduces
        // top_k's lowest-index tie-break.
        unsigned long long prefix = (unsigned long long)d0 << 56;
        unsigned long long Pstar = prefix;
        int needc = need;
        for (int pass = 0; pass < 7; ++pass) {
            const int shift = 48 - 8 * pass;
            hist[t] = 0;
            __syncthreads();
            const unsigned long long mask = ~0ull << (shift + 8);
            for (unsigned int j = t; j < nc; j += NTHREADS) {
                unsigned long long pk = cand[j];
                if ((pk & mask) == prefix)
                    atomicAdd(&hist[(unsigned int)(pk >> shift) & 255u], 1u);
            }
            __syncthreads();
            find_digit(hist, needc, t, &s_digit, &s_need, &s_cnt);
            prefix |= (unsigned long long)s_digit << shift;
            needc = s_need;
            if ((int)s_cnt == needc) {  // whole digit taken -> cutoff known
                Pstar = prefix | ((shift > 0) ? ((1ull << shift) - 1ull) : 0ull);
                break;
            }
            if (shift == 0) Pstar = prefix;
        }
        for (unsigned int j = t; j < nc; j += NTHREADS) {
            unsigned long long pk = cand[j];
            if (pk <= Pstar)
                process_point((int)(unsigned int)(pk & 0xFFFFFFFFull),
                              fp, q0x, q0y, q0z, counts);
        }
        __syncthreads();
    } else {
        // ---- Fallback (bucket overflow, statistically never): radix select
        // recomputing candidate keys each pass, filtered by the digit array.
        unsigned long long prefix = (unsigned long long)d0 << 56;
        unsigned long long Pstar = prefix;
        int needc = need;
        for (int pass = 0; pass < 7; ++pass) {
            const int shift = 48 - 8 * pass;
            hist[t] = 0;
            __syncthreads();
            const unsigned long long mask = ~0ull << (shift + 8);
            for (int w = t; w < nwords; w += NTHREADS) {
                unsigned int eq = __vcmpeq4(digw[w], d0x4);
                if (!eq) continue;
                #pragma unroll
                for (int j = 0; j < 4; ++j)
                    if ((eq >> (8 * j)) & 1u) {
                        int i = 4 * w + j;
                        if (i < n_fp) {
                            unsigned int k = compute_key(vx, vy, vz, fp, i);
                            unsigned long long pk =
                                ((unsigned long long)k << 32) |
                                (unsigned long long)(unsigned int)i;
                            if ((pk & mask) == prefix)
                                atomicAdd(
                                    &hist[(unsigned int)(pk >> shift) & 255u],
                                    1u);
                        }
                    }
            }
            __syncthreads();
            find_digit(hist, needc, t, &s_digit, &s_need, &s_cnt);
            prefix |= (unsigned long long)s_digit << shift;
            needc = s_need;
            if ((int)s_cnt == needc) {
                Pstar = prefix | ((shift > 0) ? ((1ull << shift) - 1ull) : 0ull);
                break;
            }
            if (shift == 0) Pstar = prefix;
        }
        for (int w = t; w < nwords; w += NTHREADS) {
            unsigned int eq = __vcmpeq4(digw[w], d0x4);
            if (!eq) continue;
            #pragma unroll
            for (int j = 0; j < 4; ++j)
                if ((eq >> (8 * j)) & 1u) {
                    int i = 4 * w + j;
                    if (i < n_fp) {
                        unsigned int k = compute_key(vx, vy, vz, fp, i);
                        unsigned long long pk =
                            ((unsigned long long)k << 32) |
                            (unsigned long long)(unsigned int)i;
                        if (pk <= Pstar)
                            process_point(i, fp, q0x, q0y, q0z, counts);
                    }
                }
        }
        __syncthreads();
    }

    // ---- counts+1 -> L2-normalize*4 -> softmax (warp 0).
    if (t < 32) {
        float c = (float)counts[t] + 1.0f;
        float ss = c * c;
        #pragma unroll
        for (int o = 16; o > 0; o >>= 1) ss += __shfl_xor_sync(0xFFFFFFFFu, ss, o);
        float pip = (c / sqrtf(ss)) * 4.0f;
        float m = pip;
        #pragma unroll
        for (int o = 16; o > 0; o >>= 1)
            m = fmaxf(m, __shfl_xor_sync(0xFFFFFFFFu, m, o));
        float e = expf(pip - m);
        float se = e;
        #pragma unroll
        for (int o = 16; o > 0; o >>= 1) se += __shfl_xor_sync(0xFFFFFFFFu, se, o);
        out[b * PARTS + t] = e / se;
    }
}

extern "C" void kernel_launch(void* const* d_in, const int* in_sizes, int n_in,
                              void* d_out, int out_size)
{
    const float* vp = (const float*)d_in[0];   // sampled_vehicle_points (n_vp, 3)
    const float* fp = (const float*)d_in[1];   // fusion_point          (n_fp, 3)
    float* out = (float*)d_out;                // (n_vp, 32)

    const int n_vp = in_sizes[0] / 3;
    const int n_fp = in_sizes[1] / 3;

    const size_t smem = (size_t)(((n_fp + 3) / 4) * 4);  // digit bytes (~20 KB)
    scp_topk_bins_kernel<<<n_vp, NTHREADS, smem>>>(vp, fp, out, n_fp);
}

// round 13
// speedup vs baseline: 1.3016x; 1.3016x over previous
#include <cuda_runtime.h>
#include <math.h>

#define NTHREADS 256
#define TOPK_K   200
#define PARTS    32
#define CAND_CAP 2048

// ---------------------------------------------------------------------------
// d^2 with a fixed, non-FMA operation order so pass A and pass B produce
// bit-identical keys (and match XLA's unfused sum-of-squares).
__device__ __forceinline__ unsigned int compute_key(
    float vx, float vy, float vz, const float* __restrict__ fp, int i)
{
    float dx = __fsub_rn(vx, fp[3 * i + 0]);
    float dy = __fsub_rn(vy, fp[3 * i + 1]);
    float dz = __fsub_rn(vz, fp[3 * i + 2]);
    float d2 = __fadd_rn(__fadd_rn(__fmul_rn(dx, dx), __fmul_rn(dy, dy)),
                         __fmul_rn(dz, dz));
    return __float_as_uint(d2);   // d2 >= 0, so uint order == float order
}

// Replicates the reference's per-point bin computation for rel = q_j - q_0.
__device__ __forceinline__ void process_point(
    int i, const float* __restrict__ fp,
    float q0x, float q0y, float q0z,
    unsigned int* counts)
{
    const float TWO_PI_F = 6.28318530717958647692f;
    const float PI_F     = 3.14159265358979323846f;

    float rx = __fsub_rn(fp[3 * i + 0], q0x);
    float ry = __fsub_rn(fp[3 * i + 1], q0y);
    float rz = __fsub_rn(fp[3 * i + 2], q0z);

    float axy = fmodf(atan2f(ry, rx) + TWO_PI_F, TWO_PI_F);
    float azy = fmodf(atan2f(ry, rz) + TWO_PI_F, PI_F);
    int xyb = (int)floorf(axy / (TWO_PI_F * 0.25f));
    int zyb = (int)floorf(azy / (PI_F * 0.25f));

    float d2 = __fadd_rn(__fadd_rn(__fmul_rn(rx, rx), __fmul_rn(ry, ry)),
                         __fmul_rn(rz, rz));
    float D = sqrtf(__fadd_rn(d2, 1e-7f));
    int dist = (D >= 4.0f) ? 1 : ((D >= 1.0f) ? 0 : -1);

    if (dist >= 0 && xyb >= 0 && zyb >= 0) {
        int bin = dist * 16 + xyb * 4 + zyb;
        if (bin >= 0 && bin < PARTS) atomicAdd(&counts[bin], 1u);
    }
}

// Parallel "find digit d where cumulative count reaches `need`" over a 256-bin
// histogram. Warp 0 only; result broadcast through shared. s_cnt = count in
// the chosen digit (for the early-exit check in the radix select).
__device__ __forceinline__ void find_digit(
    unsigned int* hist, int need, int t,
    unsigned int* s_digit, int* s_need, unsigned int* s_cnt)
{
    if (t < 32) {
        int base = t * 8;
        int s = 0;
        #pragma unroll
        for (int j = 0; j < 8; ++j) s += (int)hist[base + j];
        int cum = s;
        #pragma unroll
        for (int o = 1; o < 32; o <<= 1) {
            int v = __shfl_up_sync(0xFFFFFFFFu, cum, o);
            if (t >= o) cum += v;
        }
        unsigned int bal = __ballot_sync(0xFFFFFFFFu, cum >= need);
        int lane = __ffs(bal) - 1;
        if (t == lane) {
            int c = cum - s;   // exclusive prefix at this lane's first bin
            int d = base;
            while (c + (int)hist[d] < need) { c += (int)hist[d]; ++d; }
            *s_digit = (unsigned int)d;
            *s_need = need - c;
            *s_cnt = hist[d];
        }
    }
    __syncthreads();
}

__global__ __launch_bounds__(NTHREADS)
void scp_topk_bins_kernel(const float* __restrict__ vp,
                          const float* __restrict__ fp,
                          float* __restrict__ out,
                          int n_fp)
{
    __shared__ unsigned int hist[256];
    __shared__ unsigned long long cand[CAND_CAP];  // (key<<32)|idx
    __shared__ unsigned int counts[PARTS];
    __shared__ unsigned long long minpack;
    __shared__ unsigned int s_cand_count;
    __shared__ unsigned int s_digit;
    __shared__ int s_need;
    __shared__ unsigned int s_cnt;

    const int b = blockIdx.x;
    const int t = threadIdx.x;

    const float vx = vp[3 * b + 0];
    const float vy = vp[3 * b + 1];
    const float vz = vp[3 * b + 2];

    if (t < PARTS) counts[t] = 0;
    if (t == 0) { minpack = ~0ull; s_cand_count = 0; }
    hist[t] = 0;
    __syncthreads();

    const int niter = (n_fp + NTHREADS - 1) / NTHREADS;

    // ---- Pass A: digit-0 histogram (warp-aggregated) + packed argmin.
    unsigned long long lmin = ~0ull;
    #pragma unroll 4
    for (int it = 0; it < niter; ++it) {
        int i = it * NTHREADS + t;
        bool valid = (i < n_fp);
        unsigned int active = __ballot_sync(0xFFFFFFFFu, valid);
        if (valid) {
            unsigned int k = compute_key(vx, vy, vz, fp, i);
            unsigned int d = k >> 24;
            unsigned int peers = __match_any_sync(active, d);
            int leader = __ffs(peers) - 1;
            if ((int)(t & 31) == leader)
                atomicAdd(&hist[d], (unsigned int)__popc(peers));
            unsigned long long pk =
                ((unsigned long long)k << 32) | (unsigned long long)(unsigned int)i;
            if (pk < lmin) lmin = pk;
        }
    }
    atomicMin(&minpack, lmin);
    __syncthreads();

    find_digit(hist, TOPK_K, t, &s_digit, &s_need, &s_cnt);
    const unsigned int d0 = s_digit;
    int need = s_need;                     // items to take inside bucket d0

    // Anchor = nearest fusion point (lowest index on key ties).
    const unsigned int amin = (unsigned int)(minpack & 0xFFFFFFFFull);
    const float q0x = fp[3 * amin + 0];
    const float q0y = fp[3 * amin + 1];
    const float q0z = fp[3 * amin + 2];

    // ---- Pass B: rescan. digit<d0 -> process now; digit==d0 -> compact.
    #pragma unroll 4
    for (int i = t; i < n_fp; i += NTHREADS) {
        unsigned int k = compute_key(vx, vy, vz, fp, i);
        unsigned int d = k >> 24;
        if (d < d0) {
            process_point(i, fp, q0x, q0y, q0z, counts);
        } else if (d == d0) {
            unsigned int p = atomicAdd(&s_cand_count, 1u);
            if (p < CAND_CAP)
                cand[p] = ((unsigned long long)k << 32) |
                          (unsigned long long)(unsigned int)i;
        }
    }
    __syncthreads();
    const unsigned int nc = s_cand_count;

    if (nc <= CAND_CAP) {
        // ---- Main path: exact need-th smallest packed value among candidates
        // via 8-bit radix passes over the (small) candidate list, with early
        // exit when the whole digit is taken. Packed (key, index) ordering
        // reproduces top_k's lowest-index tie-break.
        unsigned long long prefix = (unsigned long long)d0 << 56;
        unsigned long long Pstar = prefix;
        int needc = need;
        for (int pass = 0; pass < 7; ++pass) {
            const int shift = 48 - 8 * pass;
            hist[t] = 0;
            __syncthreads();
            const unsigned long long mask = ~0ull << (shift + 8);
            for (unsigned int j = t; j < nc; j += NTHREADS) {
                unsigned long long pk = cand[j];
                if ((pk & mask) == prefix)
                    atomicAdd(&hist[(unsigned int)(pk >> shift) & 255u], 1u);
            }
            __syncthreads();
            find_digit(hist, needc, t, &s_digit, &s_need, &s_cnt);
            prefix |= (unsigned long long)s_digit << shift;
            needc = s_need;
            if ((int)s_cnt == needc) {  // whole digit taken -> cutoff known
                Pstar = prefix | ((shift > 0) ? ((1ull << shift) - 1ull) : 0ull);
                break;
            }
            if (shift == 0) Pstar = prefix;
        }
        for (unsigned int j = t; j < nc; j += NTHREADS) {
            unsigned long long pk = cand[j];
            if (pk <= Pstar)
                process_point((int)(unsigned int)(pk & 0xFFFFFFFFull),
                              fp, q0x, q0y, q0z, counts);
        }
        __syncthreads();
    } else {
        // ---- Fallback (statistically never): refine digits with full
        // rescans, then select with tie handling by index rank.
        unsigned int prefix = d0 << 24;
        int needf = need;
        for (int pass = 1; pass < 4; ++pass) {
            const int shift = 24 - 8 * pass;
            hist[t] = 0;
            __syncthreads();
            const unsigned int mask = 0xFFFFFFFFu << (shift + 8);
            for (int i = t; i < n_fp; i += NTHREADS) {
                unsigned int k = compute_key(vx, vy, vz, fp, i);
                if ((k & mask) == prefix)
                    atomicAdd(&hist[(k >> shift) & 255u], 1u);
            }
            __syncthreads();
            find_digit(hist, needf, t, &s_digit, &s_need, &s_cnt);
            prefix |= s_digit << shift;
            needf = s_need;
        }
        const unsigned int V = prefix;
        if (t == 0) s_cand_count = 0;
        __syncthreads();
        for (int i = t; i < n_fp; i += NTHREADS) {
            unsigned int k = compute_key(vx, vy, vz, fp, i);
            if (k >= (d0 << 24)) {   // digit<d0 already processed in pass B
                if (k < V) {
                    process_point(i, fp, q0x, q0y, q0z, counts);
                } else if (k == V) {
                    unsigned int p = atomicAdd(&s_cand_count, 1u);
                    if (p < CAND_CAP)
                        cand[p] = (unsigned long long)(unsigned int)i;
                }
            }
        }
        __syncthreads();
        unsigned int ne = min(s_cand_count, (unsigned int)CAND_CAP);
        for (unsigned int j = t; j < ne; j += NTHREADS) {
            unsigned int my = (unsigned int)cand[j];
            int rank = 0;
            for (unsigned int l = 0; l < ne; ++l)
                rank += ((unsigned int)cand[l] < my) ? 1 : 0;
            if (rank < needf)
                process_point((int)my, fp, q0x, q0y, q0z, counts);
        }
        __syncthreads();
    }

    // ---- counts+1 -> L2-normalize*4 -> softmax (warp 0).
    if (t < 32) {
        float c = (float)counts[t] + 1.0f;
        float ss = c * c;
        #pragma unroll
        for (int o = 16; o > 0; o >>= 1) ss += __shfl_xor_sync(0xFFFFFFFFu, ss, o);
        float pip = (c / sqrtf(ss)) * 4.0f;
        float m = pip;
        #pragma unroll
        for (int o = 16; o > 0; o >>= 1)
            m = fmaxf(m, __shfl_xor_sync(0xFFFFFFFFu, m, o));
        float e = expf(pip - m);
        float se = e;
        #pragma unroll
        for (int o = 16; o > 0; o >>= 1) se += __shfl_xor_sync(0xFFFFFFFFu, se, o);
        out[b * PARTS + t] = e / se;
    }
}

extern "C" void kernel_launch(void* const* d_in, const int* in_sizes, int n_in,
                              void* d_out, int out_size)
{
    const float* vp = (const float*)d_in[0];   // sampled_vehicle_points (n_vp, 3)
    const float* fp = (const float*)d_in[1];   // fusion_point          (n_fp, 3)
    float* out = (float*)d_out;                // (n_vp, 32)

    const int n_vp = in_sizes[0] / 3;
    const int n_fp = in_sizes[1] / 3;

    scp_topk_bins_kernel<<<n_vp, NTHREADS>>>(vp, fp, out, n_fp);
}

// round 14
// speedup vs baseline: 3.1504x; 2.4204x over previous
#include <cuda_runtime.h>
#include <math.h>

#define NTHREADS 256
#define TOPK_K   200
#define PARTS    32
#define CAND_CAP 2048
#define NSAMP    2048

// ---------------------------------------------------------------------------
// d^2 with a fixed, non-FMA operation order so every recompute produces
// bit-identical keys.
__device__ __forceinline__ unsigned int compute_key(
    float vx, float vy, float vz, const float* __restrict__ fp, int i)
{
    float dx = __fsub_rn(vx, fp[3 * i + 0]);
    float dy = __fsub_rn(vy, fp[3 * i + 1]);
    float dz = __fsub_rn(vz, fp[3 * i + 2]);
    float d2 = __fadd_rn(__fadd_rn(__fmul_rn(dx, dx), __fmul_rn(dy, dy)),
                         __fmul_rn(dz, dz));
    return __float_as_uint(d2);   // d2 >= 0, so uint order == float order
}

// Replicates the reference's per-point bin computation for rel = q_j - q_0.
__device__ __forceinline__ void process_point(
    int i, const float* __restrict__ fp,
    float q0x, float q0y, float q0z,
    unsigned int* counts)
{
    const float TWO_PI_F = 6.28318530717958647692f;
    const float PI_F     = 3.14159265358979323846f;

    float rx = __fsub_rn(fp[3 * i + 0], q0x);
    float ry = __fsub_rn(fp[3 * i + 1], q0y);
    float rz = __fsub_rn(fp[3 * i + 2], q0z);

    float axy = fmodf(atan2f(ry, rx) + TWO_PI_F, TWO_PI_F);
    float azy = fmodf(atan2f(ry, rz) + TWO_PI_F, PI_F);
    int xyb = (int)floorf(axy / (TWO_PI_F * 0.25f));
    int zyb = (int)floorf(azy / (PI_F * 0.25f));

    float d2 = __fadd_rn(__fadd_rn(__fmul_rn(rx, rx), __fmul_rn(ry, ry)),
                         __fmul_rn(rz, rz));
    float D = sqrtf(__fadd_rn(d2, 1e-7f));
    int dist = (D >= 4.0f) ? 1 : ((D >= 1.0f) ? 0 : -1);

    if (dist >= 0 && xyb >= 0 && zyb >= 0) {
        int bin = dist * 16 + xyb * 4 + zyb;
        if (bin >= 0 && bin < PARTS) atomicAdd(&counts[bin], 1u);
    }
}

// Parallel "digit where cumulative count reaches `need`" over a 256-bin
// histogram. Warp 0 computes; results broadcast via shared. Caller guarantees
// 1 <= need <= sum(hist).
__device__ __forceinline__ void find_digit(
    unsigned int* hist, int need, int t,
    unsigned int* s_digit, int* s_need, unsigned int* s_cnt)
{
    if (t < 32) {
        int base = t * 8;
        int s = 0;
        #pragma unroll
        for (int j = 0; j < 8; ++j) s += (int)hist[base + j];
        int cum = s;
        #pragma unroll
        for (int o = 1; o < 32; o <<= 1) {
            int v = __shfl_up_sync(0xFFFFFFFFu, cum, o);
            if (t >= o) cum += v;
        }
        unsigned int bal = __ballot_sync(0xFFFFFFFFu, cum >= need);
        int lane = __ffs(bal) - 1;
        if (t == lane) {
            int c = cum - s;   // exclusive prefix at this lane's first bin
            int d = base;
            while (c + (int)hist[d] < need) { c += (int)hist[d]; ++d; }
            *s_digit = (unsigned int)d;
            *s_need = need - c;
            *s_cnt = hist[d];
        }
    }
    __syncthreads();
}

__global__ __launch_bounds__(NTHREADS)
void scp_topk_bins_kernel(const float* __restrict__ vp,
                          const float* __restrict__ fp,
                          float* __restrict__ out,
                          int n_fp)
{
    __shared__ unsigned int hist[256];
    __shared__ unsigned long long cand[CAND_CAP];  // (key<<32)|idx
    __shared__ unsigned int counts[PARTS];
    __shared__ unsigned long long minpack;
    __shared__ unsigned int s_cand_count;
    __shared__ unsigned int s_digit;
    __shared__ int s_need;
    __shared__ unsigned int s_cnt;

    unsigned int* const skey = (unsigned int*)cand;   // sample keys (phase 1)

    const int b = blockIdx.x;
    const int t = threadIdx.x;

    const float vx = vp[3 * b + 0];
    const float vy = vp[3 * b + 1];
    const float vz = vp[3 * b + 2];

    if (t < PARTS) counts[t] = 0;
    if (t == 0) { minpack = ~0ull; s_cand_count = 0; }
    __syncthreads();

    const int needK = (n_fp < TOPK_K) ? n_fp : TOPK_K;

    // ---- Phase 1: pivot = exact sample order statistic (FULL 32-bit key
    // granularity -- immune to the concentrated-distance failure that killed
    // digit-granularity pivots). Sample NSAMP keys, exact rank-R select.
    unsigned int pivot = 0xFFFFFFFFu;
    if (n_fp > CAND_CAP) {
        const int stride = n_fp / NSAMP;           // >= 1
        for (int j = t; j < NSAMP; j += NTHREADS)
            skey[j] = compute_key(vx, vy, vz, fp, j * stride);
        __syncthreads();
        int R = (int)(((long long)NSAMP * 900) / n_fp);
        if (R < 1) R = 1;
        // Exact rank-R key among the samples: 4x 8-bit radix passes.
        unsigned int spre = 0;
        int sneed = R;
        for (int pass = 0; pass < 4; ++pass) {
            const int shift = 24 - 8 * pass;
            hist[t] = 0;
            __syncthreads();
            const unsigned int mask =
                (pass == 0) ? 0u : (0xFFFFFFFFu << (shift + 8));
            for (int j = t; j < NSAMP; j += NTHREADS) {
                unsigned int k = skey[j];
                if ((k & mask) == spre)
                    atomicAdd(&hist[(k >> shift) & 255u], 1u);
            }
            __syncthreads();
            find_digit(hist, sneed, t, &s_digit, &s_need, &s_cnt);
            spre |= s_digit << shift;
            sneed = s_need;
        }
        pivot = (spre == 0xFFFFFFFFu) ? 0xFFFFFFFFu : spre + 1u;
        __syncthreads();   // sample buffer dead before cand reuse
    }

    // ---- Phase 2: ONE lean full scan: running min + compact keys < pivot.
    {
        unsigned int kmin = 0xFFFFFFFFu;
        unsigned int imin = 0;
        #pragma unroll 4
        for (int i = t; i < n_fp; i += NTHREADS) {
            unsigned int k = compute_key(vx, vy, vz, fp, i);
            if (k < kmin) { kmin = k; imin = (unsigned int)i; }
            if (k < pivot) {
                unsigned int p = atomicAdd(&s_cand_count, 1u);
                if (p < CAND_CAP)
                    cand[p] = ((unsigned long long)k << 32) |
                              (unsigned long long)(unsigned int)i;
            }
        }
        unsigned long long lmin =
            ((unsigned long long)kmin << 32) | (unsigned long long)imin;
        #pragma unroll
        for (int o = 16; o > 0; o >>= 1) {
            unsigned long long v = __shfl_xor_sync(0xFFFFFFFFu, lmin, o);
            if (v < lmin) lmin = v;
        }
        if ((t & 31) == 0) atomicMin(&minpack, lmin);
    }
    __syncthreads();
    const unsigned int nc = s_cand_count;
    const bool fast_ok = (nc >= (unsigned int)needK &&
                          nc <= (unsigned int)CAND_CAP);

    // Anchor = nearest fusion point (lowest index on key ties).
    const unsigned int amin = (unsigned int)(minpack & 0xFFFFFFFFull);
    const float q0x = fp[3 * amin + 0];
    const float q0y = fp[3 * amin + 1];
    const float q0z = fp[3 * amin + 2];

    if (fast_ok) {
        // ---- Phase 3 (fast): exact needK-th smallest packed (key,idx) via
        // 8-bit radix passes with early exit (validated R10/R13). Packed
        // ordering reproduces top_k's lowest-index tie-break.
        unsigned long long prefix = 0ull;
        unsigned long long Pstar = 0ull;
        int needc = needK;
        for (int pass = 0; pass < 8; ++pass) {
            const int shift = 56 - 8 * pass;
            hist[t] = 0;
            __syncthreads();
            const unsigned long long mask =
                (pass == 0) ? 0ull : (~0ull << (shift + 8));
            for (unsigned int j = t; j < nc; j += NTHREADS) {
                unsigned long long pk = cand[j];
                if ((pk & mask) == prefix)
                    atomicAdd(&hist[(unsigned int)(pk >> shift) & 255u], 1u);
            }
            __syncthreads();
            find_digit(hist, needc, t, &s_digit, &s_need, &s_cnt);
            prefix |= (unsigned long long)s_digit << shift;
            needc = s_need;
            if ((int)s_cnt == needc) {
                Pstar = prefix | ((shift > 0) ? ((1ull << shift) - 1ull) : 0ull);
                break;
            }
            if (shift == 0) Pstar = prefix;
        }
        for (unsigned int j = t; j < nc; j += NTHREADS) {
            unsigned long long pk = cand[j];
            if (pk <= Pstar)
                process_point((int)(unsigned int)(pk & 0xFFFFFFFFull),
                              fp, q0x, q0y, q0z, counts);
        }
        __syncthreads();
    } else {
        // ---- Slow path (probability ~0, but fully correct): the entire
        // proven R13 algorithm from scratch. counts[] is still all-zero here.
        hist[t] = 0;
        if (t == 0) s_cand_count = 0;
        __syncthreads();

        const int niter = (n_fp + NTHREADS - 1) / NTHREADS;
        // Pass A: exact digit-0 histogram (warp-aggregated).
        for (int it = 0; it < niter; ++it) {
            int i = it * NTHREADS + t;
            bool valid = (i < n_fp);
            unsigned int active = __ballot_sync(0xFFFFFFFFu, valid);
            if (valid) {
                unsigned int k = compute_key(vx, vy, vz, fp, i);
                unsigned int d = k >> 24;
                unsigned int peers = __match_any_sync(active, d);
                if ((int)(t & 31) == __ffs(peers) - 1)
                    atomicAdd(&hist[d], (unsigned int)__popc(peers));
            }
        }
        __syncthreads();
        find_digit(hist, needK, t, &s_digit, &s_need, &s_cnt);
        const unsigned int d0 = s_digit;
        const int need = s_need;

        // Pass B: digit<d0 -> process; digit==d0 -> compact.
        for (int i = t; i < n_fp; i += NTHREADS) {
            unsigned int k = compute_key(vx, vy, vz, fp, i);
            unsigned int d = k >> 24;
            if (d < d0) {
                process_point(i, fp, q0x, q0y, q0z, counts);
            } else if (d == d0) {
                unsigned int p = atomicAdd(&s_cand_count, 1u);
                if (p < CAND_CAP)
                    cand[p] = ((unsigned long long)k << 32) |
                              (unsigned long long)(unsigned int)i;
            }
        }
        __syncthreads();
        const unsigned int nc2 = s_cand_count;

        if (nc2 <= CAND_CAP) {
            unsigned long long prefix = (unsigned long long)d0 << 56;
            unsigned long long Pstar = prefix;
            int needc = need;
            for (int pass = 0; pass < 7; ++pass) {
                const int shift = 48 - 8 * pass;
                hist[t] = 0;
                __syncthreads();
                const unsigned long long mask = ~0ull << (shift + 8);
                for (unsigned int j = t; j < nc2; j += NTHREADS) {
                    unsigned long long pk = cand[j];
                    if ((pk & mask) == prefix)
                        atomicAdd(&hist[(unsigned int)(pk >> shift) & 255u], 1u);
                }
                __syncthreads();
                find_digit(hist, needc, t, &s_digit, &s_need, &s_cnt);
                prefix |= (unsigned long long)s_digit << shift;
                needc = s_need;
                if ((int)s_cnt == needc) {
                    Pstar = prefix |
                            ((shift > 0) ? ((1ull << shift) - 1ull) : 0ull);
                    break;
                }
                if (shift == 0) Pstar = prefix;
            }
            for (unsigned int j = t; j < nc2; j += NTHREADS) {
                unsigned long long pk = cand[j];
                if (pk <= Pstar)
                    process_point((int)(unsigned int)(pk & 0xFFFFFFFFull),
                                  fp, q0x, q0y, q0z, counts);
            }
            __syncthreads();
        } else {
            // Full-granularity refinement with full rescans (R3/R13-proven).
            unsigned int prefix = d0 << 24;
            int needf = need;
            for (int pass = 1; pass < 4; ++pass) {
                const int shift = 24 - 8 * pass;
                hist[t] = 0;
                __syncthreads();
                const unsigned int mask = 0xFFFFFFFFu << (shift + 8);
                for (int i = t; i < n_fp; i += NTHREADS) {
                    unsigned int k = compute_key(vx, vy, vz, fp, i);
                    if ((k & mask) == prefix)
                        atomicAdd(&hist[(k >> shift) & 255u], 1u);
                }
                __syncthreads();
                find_digit(hist, needf, t, &s_digit, &s_need, &s_cnt);
                prefix |= s_digit << shift;
                needf = s_need;
            }
            const unsigned int V = prefix;
            if (t == 0) s_cand_count = 0;
            __syncthreads();
            for (int i = t; i < n_fp; i += NTHREADS) {
                unsigned int k = compute_key(vx, vy, vz, fp, i);
                if (k >= (d0 << 24)) {
                    if (k < V) {
                        process_point(i, fp, q0x, q0y, q0z, counts);
                    } else if (k == V) {
                        unsigned int p = atomicAdd(&s_cand_count, 1u);
                        if (p < CAND_CAP)
                            cand[p] = (unsigned long long)(unsigned int)i;
                    }
                }
            }
            __syncthreads();
            unsigned int ne = min(s_cand_count, (unsigned int)CAND_CAP);
            for (unsigned int j = t; j < ne; j += NTHREADS) {
                unsigned int my = (unsigned int)cand[j];
                int rank = 0;
                for (unsigned int l = 0; l < ne; ++l)
                    rank += ((unsigned int)cand[l] < my) ? 1 : 0;
                if (rank < needf)
                    process_point((int)my, fp, q0x, q0y, q0z, counts);
            }
            __syncthreads();
        }
    }

    // ---- counts+1 -> L2-normalize*4 -> softmax (warp 0).
    if (t < 32) {
        float c = (float)counts[t] + 1.0f;
        float ss = c * c;
        #pragma unroll
        for (int o = 16; o > 0; o >>= 1) ss += __shfl_xor_sync(0xFFFFFFFFu, ss, o);
        float pip = (c / sqrtf(ss)) * 4.0f;
        float m = pip;
        #pragma unroll
        for (int o = 16; o > 0; o >>= 1)
            m = fmaxf(m, __shfl_xor_sync(0xFFFFFFFFu, m, o));
        float e = expf(pip - m);
        float se = e;
        #pragma unroll
        for (int o = 16; o > 0; o >>= 1) se += __shfl_xor_sync(0xFFFFFFFFu, se, o);
        out[b * PARTS + t] = e / se;
    }
}

extern "C" void kernel_launch(void* const* d_in, const int* in_sizes, int n_in,
                              void* d_out, int out_size)
{
    const float* vp = (const float*)d_in[0];   // sampled_vehicle_points (n_vp, 3)
    const float* fp = (const float*)d_in[1];   // fusion_point          (n_fp, 3)
    float* out = (float*)d_out;                // (n_vp, 32)

    const int n_vp = in_sizes[0] / 3;
    const int n_fp = in_sizes[1] / 3;

    scp_topk_bins_kernel<<<n_vp, NTHREADS>>>(vp, fp, out, n_fp);
}

// round 17
// speedup vs baseline: 3.4375x; 1.0911x over previous
#include <cuda_runtime.h>
#include <math.h>

#define NTHREADS 256
#define TOPK_K   200
#define PARTS    32
#define CAND_CAP 2048
#define NSAMP    2048

// ---------------------------------------------------------------------------
// d^2 with a fixed, non-FMA operation order so every recompute produces
// bit-identical keys.
__device__ __forceinline__ unsigned int key_xyz(
    float vx, float vy, float vz, float px, float py, float pz)
{
    float dx = __fsub_rn(vx, px);
    float dy = __fsub_rn(vy, py);
    float dz = __fsub_rn(vz, pz);
    float d2 = __fadd_rn(__fadd_rn(__fmul_rn(dx, dx), __fmul_rn(dy, dy)),
                         __fmul_rn(dz, dz));
    return __float_as_uint(d2);   // d2 >= 0, so uint order == float order
}

__device__ __forceinline__ unsigned int compute_key(
    float vx, float vy, float vz, const float* __restrict__ fp, int i)
{
    return key_xyz(vx, vy, vz, fp[3 * i + 0], fp[3 * i + 1], fp[3 * i + 2]);
}

// Replicates the reference's per-point bin computation for rel = q_j - q_0.
__device__ __forceinline__ void process_point(
    int i, const float* __restrict__ fp,
    float q0x, float q0y, float q0z,
    unsigned int* counts)
{
    const float TWO_PI_F = 6.28318530717958647692f;
    const float PI_F     = 3.14159265358979323846f;

    float rx = __fsub_rn(fp[3 * i + 0], q0x);
    float ry = __fsub_rn(fp[3 * i + 1], q0y);
    float rz = __fsub_rn(fp[3 * i + 2], q0z);

    float axy = fmodf(atan2f(ry, rx) + TWO_PI_F, TWO_PI_F);
    float azy = fmodf(atan2f(ry, rz) + TWO_PI_F, PI_F);
    int xyb = (int)floorf(axy / (TWO_PI_F * 0.25f));
    int zyb = (int)floorf(azy / (PI_F * 0.25f));

    float d2 = __fadd_rn(__fadd_rn(__fmul_rn(rx, rx), __fmul_rn(ry, ry)),
                         __fmul_rn(rz, rz));
    float D = sqrtf(__fadd_rn(d2, 1e-7f));
    int dist = (D >= 4.0f) ? 1 : ((D >= 1.0f) ? 0 : -1);

    if (dist >= 0 && xyb >= 0 && zyb >= 0) {
        int bin = dist * 16 + xyb * 4 + zyb;
        if (bin >= 0 && bin < PARTS) atomicAdd(&counts[bin], 1u);
    }
}

// Parallel "digit where cumulative count reaches `need`" over a 256-bin
// histogram. Warp 0 computes; results broadcast via shared. Caller guarantees
// 1 <= need <= sum(hist).
__device__ __forceinline__ void find_digit(
    unsigned int* hist, int need, int t,
    unsigned int* s_digit, int* s_need, unsigned int* s_cnt)
{
    if (t < 32) {
        int base = t * 8;
        int s = 0;
        #pragma unroll
        for (int j = 0; j < 8; ++j) s += (int)hist[base + j];
        int cum = s;
        #pragma unroll
        for (int o = 1; o < 32; o <<= 1) {
            int v = __shfl_up_sync(0xFFFFFFFFu, cum, o);
            if (t >= o) cum += v;
        }
        unsigned int bal = __ballot_sync(0xFFFFFFFFu, cum >= need);
        int lane = __ffs(bal) - 1;
        if (t == lane) {
            int c = cum - s;   // exclusive prefix at this lane's first bin
            int d = base;
            while (c + (int)hist[d] < need) { c += (int)hist[d]; ++d; }
            *s_digit = (unsigned int)d;
            *s_need = need - c;
            *s_cnt = hist[d];
        }
    }
    __syncthreads();
}

__global__ __launch_bounds__(NTHREADS)
void scp_topk_bins_kernel(const float* __restrict__ vp,
                          const float* __restrict__ fp,
                          float* __restrict__ out,
                          int n_fp)
{
    __shared__ unsigned int hist[256];
    __shared__ unsigned long long cand[CAND_CAP];  // (key<<32)|idx
    __shared__ unsigned int counts[PARTS];
    __shared__ unsigned long long minpack;
    __shared__ unsigned int s_cand_count;
    __shared__ unsigned int s_digit;
    __shared__ int s_need;
    __shared__ unsigned int s_cnt;

    unsigned int* const skey = (unsigned int*)cand;   // sample keys (phase 1)

    const int b = blockIdx.x;
    const int t = threadIdx.x;

    const float vx = vp[3 * b + 0];
    const float vy = vp[3 * b + 1];
    const float vz = vp[3 * b + 2];

    if (t < PARTS) counts[t] = 0;
    if (t == 0) { minpack = ~0ull; s_cand_count = 0; }
    __syncthreads();

    const int needK = (n_fp < TOPK_K) ? n_fp : TOPK_K;
    const float4* __restrict__ fp4 = (const float4*)fp;

    // ---- Phase 1: pivot = exact sample order statistic at FULL 32-bit key
    // granularity (immune to concentrated-distance distributions). Sample =
    // first NSAMP points (iid input => valid sample), contiguous float4 loads.
    unsigned int pivot = 0xFFFFFFFFu;
    if (n_fp > CAND_CAP) {
        for (int g = t; g < NSAMP / 4; g += NTHREADS) {
            float4 A = fp4[g * 3 + 0];
            float4 B = fp4[g * 3 + 1];
            float4 C = fp4[g * 3 + 2];
            skey[g * 4 + 0] = key_xyz(vx, vy, vz, A.x, A.y, A.z);
            skey[g * 4 + 1] = key_xyz(vx, vy, vz, A.w, B.x, B.y);
            skey[g * 4 + 2] = key_xyz(vx, vy, vz, B.z, B.w, C.x);
            skey[g * 4 + 3] = key_xyz(vx, vy, vz, C.y, C.z, C.w);
        }
        __syncthreads();
        int R = (int)(((long long)NSAMP * 900) / n_fp);
        if (R < 1) R = 1;
        // Exact rank-R key among the samples: 4x 8-bit radix passes.
        unsigned int spre = 0;
        int sneed = R;
        for (int pass = 0; pass < 4; ++pass) {
            const int shift = 24 - 8 * pass;
            hist[t] = 0;
            __syncthreads();
            const unsigned int mask =
                (pass == 0) ? 0u : (0xFFFFFFFFu << (shift + 8));
            for (int j = t; j < NSAMP; j += NTHREADS) {
                unsigned int k = skey[j];
                if ((k & mask) == spre)
                    atomicAdd(&hist[(k >> shift) & 255u], 1u);
            }
            __syncthreads();
            find_digit(hist, sneed, t, &s_digit, &s_need, &s_cnt);
            spre |= s_digit << shift;
            sneed = s_need;
        }
        pivot = (spre == 0xFFFFFFFFu) ? 0xFFFFFFFFu : spre + 1u;
        __syncthreads();   // sample buffer dead before cand reuse
    }

    // ---- Phase 2: ONE lean full scan, float4 loads (4 points / 3 LDG.128):
    // running min + compact keys < pivot (rarely-taken aggregated branch).
    {
        const int ngroups = n_fp >> 2;
        const int rem = n_fp & 3;
        unsigned int kmin = 0xFFFFFFFFu;
        unsigned int imin = 0;
        for (int g = t; g < ngroups; g += NTHREADS) {
            float4 A = fp4[g * 3 + 0];
            float4 B = fp4[g * 3 + 1];
            float4 C = fp4[g * 3 + 2];
            unsigned int k0 = key_xyz(vx, vy, vz, A.x, A.y, A.z);
            unsigned int k1 = key_xyz(vx, vy, vz, A.w, B.x, B.y);
            unsigned int k2 = key_xyz(vx, vy, vz, B.z, B.w, C.x);
            unsigned int k3 = key_xyz(vx, vy, vz, C.y, C.z, C.w);

            const unsigned int base = (unsigned int)g * 4u;
            if (k0 < kmin) { kmin = k0; imin = base + 0; }
            if (k1 < kmin) { kmin = k1; imin = base + 1; }
            if (k2 < kmin) { kmin = k2; imin = base + 2; }
            if (k3 < kmin) { kmin = k3; imin = base + 3; }

            // Aggregate the (rare) candidate test into one branch.
            if ((k0 < pivot) | (k1 < pivot) | (k2 < pivot) | (k3 < pivot)) {
                if (k0 < pivot) {
                    unsigned int p = atomicAdd(&s_cand_count, 1u);
                    if (p < CAND_CAP)
                        cand[p] = ((unsigned long long)k0 << 32) | (base + 0);
                }
                if (k1 < pivot) {
                    unsigned int p = atomicAdd(&s_cand_count, 1u);
                    if (p < CAND_CAP)
                        cand[p] = ((unsigned long long)k1 << 32) | (base + 1);
                }
                if (k2 < pivot) {
                    unsigned int p = atomicAdd(&s_cand_count, 1u);
                    if (p < CAND_CAP)
                        cand[p] = ((unsigned long long)k2 << 32) | (base + 2);
                }
                if (k3 < pivot) {
                    unsigned int p = atomicAdd(&s_cand_count, 1u);
                    if (p < CAND_CAP)
                        cand[p] = ((unsigned long long)k3 << 32) | (base + 3);
                }
            }
        }
        if (t < rem) {   // tail points
            int i = ngroups * 4 + t;
            unsigned int k = compute_key(vx, vy, vz, fp, i);
            if (k < kmin) { kmin = k; imin = (unsigned int)i; }
            if (k < pivot) {
                unsigned int p = atomicAdd(&s_cand_count, 1u);
                if (p < CAND_CAP)
                    cand[p] = ((unsigned long long)k << 32) | (unsigned int)i;
            }
        }
        unsigned long long lmin =
            ((unsigned long long)kmin << 32) | (unsigned long long)imin;
        #pragma unroll
        for (int o = 16; o > 0; o >>= 1) {
            unsigned long long v = __shfl_xor_sync(0xFFFFFFFFu, lmin, o);
            if (v < lmin) lmin = v;
        }
        if ((t & 31) == 0) atomicMin(&minpack, lmin);
    }
    __syncthreads();
    const unsigned int nc = s_cand_count;
    const bool fast_ok = (nc >= (unsigned int)needK &&
                          nc <= (unsigned int)CAND_CAP);

    // Anchor = nearest fusion point (lowest index on key ties).
    const unsigned int amin = (unsigned int)(minpack & 0xFFFFFFFFull);
    const float q0x = fp[3 * amin + 0];
    const float q0y = fp[3 * amin + 1];
    const float q0z = fp[3 * amin + 2];

    if (fast_ok) {
        // ---- Phase 3 (fast): exact needK-th smallest packed (key,idx) via
        // 8-bit radix passes with early exit. Packed ordering reproduces
        // top_k's lowest-index tie-break.
        unsigned long long prefix = 0ull;
        unsigned long long Pstar = 0ull;
        int needc = needK;
        for (int pass = 0; pass < 8; ++pass) {
            const int shift = 56 - 8 * pass;
            hist[t] = 0;
            __syncthreads();
            const unsigned long long mask =
                (pass == 0) ? 0ull : (~0ull << (shift + 8));
            for (unsigned int j = t; j < nc; j += NTHREADS) {
                unsigned long long pk = cand[j];
                if ((pk & mask) == prefix)
                    atomicAdd(&hist[(unsigned int)(pk >> shift) & 255u], 1u);
            }
            __syncthreads();
            find_digit(hist, needc, t, &s_digit, &s_need, &s_cnt);
            prefix |= (unsigned long long)s_digit << shift;
            needc = s_need;
            if ((int)s_cnt == needc) {
                Pstar = prefix | ((shift > 0) ? ((1ull << shift) - 1ull) : 0ull);
                break;
            }
            if (shift == 0) Pstar = prefix;
        }
        for (unsigned int j = t; j < nc; j += NTHREADS) {
            unsigned long long pk = cand[j];
            if (pk <= Pstar)
                process_point((int)(unsigned int)(pk & 0xFFFFFFFFull),
                              fp, q0x, q0y, q0z, counts);
        }
        __syncthreads();
    } else {
        // ---- Slow path (probability ~0, fully correct): entire proven R13
        // algorithm from scratch. counts[] is still all-zero here.
        hist[t] = 0;
        if (t == 0) s_cand_count = 0;
        __syncthreads();

        const int niter = (n_fp + NTHREADS - 1) / NTHREADS;
        for (int it = 0; it < niter; ++it) {
            int i = it * NTHREADS + t;
            bool valid = (i < n_fp);
            unsigned int active = __ballot_sync(0xFFFFFFFFu, valid);
            if (valid) {
                unsigned int k = compute_key(vx, vy, vz, fp, i);
                unsigned int d = k >> 24;
                unsigned int peers = __match_any_sync(active, d);
                if ((int)(t & 31) == __ffs(peers) - 1)
                    atomicAdd(&hist[d], (unsigned int)__popc(peers));
            }
        }
        __syncthreads();
        find_digit(hist, needK, t, &s_digit, &s_need, &s_cnt);
        const unsigned int d0 = s_digit;
        const int need = s_need;

        for (int i = t; i < n_fp; i += NTHREADS) {
            unsigned int k = compute_key(vx, vy, vz, fp, i);
            unsigned int d = k >> 24;
            if (d < d0) {
                process_point(i, fp, q0x, q0y, q0z, counts);
            } else if (d == d0) {
                unsigned int p = atomicAdd(&s_cand_count, 1u);
                if (p < CAND_CAP)
                    cand[p] = ((unsigned long long)k << 32) |
                              (unsigned long long)(unsigned int)i;
            }
        }
        __syncthreads();
        const unsigned int nc2 = s_cand_count;

        if (nc2 <= CAND_CAP) {
            unsigned long long prefix = (unsigned long long)d0 << 56;
            unsigned long long Pstar = prefix;
            int needc = need;
            for (int pass = 0; pass < 7; ++pass) {
                const int shift = 48 - 8 * pass;
                hist[t] = 0;
                __syncthreads();
                const unsigned long long mask = ~0ull << (shift + 8);
                for (unsigned int j = t; j < nc2; j += NTHREADS) {
                    unsigned long long pk = cand[j];
                    if ((pk & mask) == prefix)
                        atomicAdd(&hist[(unsigned int)(pk >> shift) & 255u], 1u);
                }
                __syncthreads();
                find_digit(hist, needc, t, &s_digit, &s_need, &s_cnt);
                prefix |= (unsigned long long)s_digit << shift;
                needc = s_need;
                if ((int)s_cnt == needc) {
                    Pstar = prefix |
                            ((shift > 0) ? ((1ull << shift) - 1ull) : 0ull);
                    break;
                }
                if (shift == 0) Pstar = prefix;
            }
            for (unsigned int j = t; j < nc2; j += NTHREADS) {
                unsigned long long pk = cand[j];
                if (pk <= Pstar)
                    process_point((int)(unsigned int)(pk & 0xFFFFFFFFull),
                                  fp, q0x, q0y, q0z, counts);
            }
            __syncthreads();
        } else {
            unsigned int prefix = d0 << 24;
            int needf = need;
            for (int pass = 1; pass < 4; ++pass) {
                const int shift = 24 - 8 * pass;
                hist[t] = 0;
                __syncthreads();
                const unsigned int mask = 0xFFFFFFFFu << (shift + 8);
                for (int i = t; i < n_fp; i += NTHREADS) {
                    unsigned int k = compute_key(vx, vy, vz, fp, i);
                    if ((k & mask) == prefix)
                        atomicAdd(&hist[(k >> shift) & 255u], 1u);
                }
                __syncthreads();
                find_digit(hist, needf, t, &s_digit, &s_need, &s_cnt);
                prefix |= s_digit << shift;
                needf = s_need;
            }
            const unsigned int V = prefix;
            if (t == 0) s_cand_count = 0;
            __syncthreads();
            for (int i = t; i < n_fp; i += NTHREADS) {
                unsigned int k = compute_key(vx, vy, vz, fp, i);
                if (k >= (d0 << 24)) {
                    if (k < V) {
                        process_point(i, fp, q0x, q0y, q0z, counts);
                    } else if (k == V) {
                        unsigned int p = atomicAdd(&s_cand_count, 1u);
                        if (p < CAND_CAP)
                            cand[p] = (unsigned long long)(unsigned int)i;
                    }
                }
            }
            __syncthreads();
            unsigned int ne = min(s_cand_count, (unsigned int)CAND_CAP);
            for (unsigned int j = t; j < ne; j += NTHREADS) {
                unsigned int my = (unsigned int)cand[j];
                int rank = 0;
                for (unsigned int l = 0; l < ne; ++l)
                    rank += ((unsigned int)cand[l] < my) ? 1 : 0;
                if (rank < needf)
                    process_point((int)my, fp, q0x, q0y, q0z, counts);
            }
            __syncthreads();
        }
    }

    // ---- counts+1 -> L2-normalize*4 -> softmax (warp 0).
    if (t < 32) {
        float c = (float)counts[t] + 1.0f;
        float ss = c * c;
        #pragma unroll
        for (int o = 16; o > 0; o >>= 1) ss += __shfl_xor_sync(0xFFFFFFFFu, ss, o);
        float pip = (c / sqrtf(ss)) * 4.0f;
        float m = pip;
        #pragma unroll
        for (int o = 16; o > 0; o >>= 1)
            m = fmaxf(m, __shfl_xor_sync(0xFFFFFFFFu, m, o));
        float e = expf(pip - m);
        float se = e;
        #pragma unroll
        for (int o = 16; o > 0; o >>= 1) se += __shfl_xor_sync(0xFFFFFFFFu, se, o);
        out[b * PARTS + t] = e / se;
    }
}

extern "C" void kernel_launch(void* const* d_in, const int* in_sizes, int n_in,
                              void* d_out, int out_size)
{
    const float* vp = (const float*)d_in[0];   // sampled_vehicle_points (n_vp, 3)
    const float* fp = (const float*)d_in[1];   // fusion_point          (n_fp, 3)
    float* out = (float*)d_out;                // (n_vp, 32)

    const int n_vp = in_sizes[0] / 3;
    const int n_fp = in_sizes[1] / 3;

    scp_topk_bins_kernel<<<n_vp, NTHREADS>>>(vp, fp, out, n_fp);
}